// round 13
// baseline (speedup 1.0000x reference)
#include <cuda_runtime.h>
#include <cuda_bf16.h>
#include <math.h>
#include <stdint.h>

// Problem constants
#define BSZ   64
#define LSEQ  100
#define LP1   101
#define DIM   64
#define NCOL  (BSZ * LP1)   // 6464
#define NROW  (BSZ * LSEQ)  // 6400
#define NCOLP 6656          // padded compacted-col bound (52 * 128)
#define NEG10K (-10000.0f)
#define LOG2E 1.4426950408889634f
#define NCH   5             // N chunk-slices; 50*5=250 CTAs, fully resident @2/SM
#define TOTAL_CTAS (50 * NCH)

// ---------------- scratch (__device__ globals; no allocs) ----------------
__device__ float  g_keep[BSZ * NCOLP];    // -log2(pop) or -inf per (batch, padded col)
__device__ uint4  g_Afrag4[NROW * 8];     // bf16(prec*log2e), m16n8k16 fragment order
__device__ uint4  g_Bfrag4[NCOLP * 8];    // bf16 compacted embs, fragment order
__device__ float  g_tgt[NROW];
__device__ float  g_partS[NCH * NROW];    // [chunk][row]
__device__ double g_rn[50];
__device__ double g_rd[50];
__device__ unsigned int g_bar;            // grid barrier counter (self-resetting)
__device__ unsigned int g_mctr[50];       // per-m-tile tickets (self-resetting)
__device__ unsigned int g_fin;            // finalizer ticket (self-resetting)

// ---------------- PTX helpers ----------------
__device__ __forceinline__ uint32_t smem_u32(const void* p) {
    uint32_t a;
    asm("{ .reg .u64 t; cvta.to.shared.u64 t, %1; cvt.u32.u64 %0, t; }" : "=r"(a) : "l"(p));
    return a;
}
__device__ __forceinline__ uint32_t pk2(float lo, float hi) {  // bf16x2, RN (unbiased)
    __nv_bfloat162 h = __floats2bfloat162_rn(lo, hi);
    return *(uint32_t*)&h;
}
__device__ __forceinline__ float ex2f(float x) {               // 2^x, -inf -> 0
    float y;
    asm("ex2.approx.f32 %0, %1;" : "=f"(y) : "f"(x));
    return y;
}
__device__ __forceinline__ void cp16(uint32_t dst, const void* src) {
    asm volatile("cp.async.ca.shared.global [%0], [%1], 16;" :: "r"(dst), "l"(src) : "memory");
}
#define CP_COMMIT()  asm volatile("cp.async.commit_group;" ::: "memory")
#define CP_WAIT0()   asm volatile("cp.async.wait_group 0;" ::: "memory")
#define CP_WAIT1()   asm volatile("cp.async.wait_group 1;" ::: "memory")
#define CP_WAIT2()   asm volatile("cp.async.wait_group 2;" ::: "memory")

__device__ __forceinline__ void mma16(float* c, uint4 a, uint32_t b0, uint32_t b1) {
    asm volatile("mma.sync.aligned.m16n8k16.row.col.f32.bf16.bf16.f32 "
        "{%0,%1,%2,%3}, {%4,%5,%6,%7}, {%8,%9}, {%0,%1,%2,%3};"
        : "+f"(c[0]), "+f"(c[1]), "+f"(c[2]), "+f"(c[3])
        : "r"(a.x), "r"(a.y), "r"(a.z), "r"(a.w), "r"(b0), "r"(b1));
}

// Grid-wide barrier (all 250 CTAs resident by construction).
__device__ __forceinline__ void gsync(unsigned int target) {
    __threadfence();
    __syncthreads();
    if (threadIdx.x == 0) {
        atomicAdd(&g_bar, 1u);
        while (*(volatile unsigned int*)&g_bar < target) { __nanosleep(32); }
    }
    __syncthreads();
}

// Local (per-CTA) compacted-column map into smem; returns nv. 512 threads.
__device__ __forceinline__ int local_compact(const int* __restrict__ log_mask,
                                             int* colid_s) {
    __shared__ int cnt[64];
    __shared__ int off[64];
    __shared__ int s_nv;
    int t = threadIdx.x, w = t >> 5, lane = t & 31;
    #pragma unroll
    for (int s = 0; s < 4; s++) {
        int b = 4 * w + s;
        int c = 0;
        #pragma unroll
        for (int ch = 0; ch < 4; ch++) {
            int pos = ch * 32 + lane;
            int flag = 0;
            if (pos <= LSEQ) flag = (pos == LSEQ) ? 1 : (log_mask[b * LSEQ + pos] != 0);
            c += __popc(__ballot_sync(0xffffffffu, flag));
        }
        if (lane == 0) cnt[b] = c;
    }
    __syncthreads();
    if (w == 0) {
        int c0 = cnt[2 * lane], c1 = cnt[2 * lane + 1];
        int s = c0 + c1, sc = s;
        #pragma unroll
        for (int o = 1; o < 32; o <<= 1) {
            int u = __shfl_up_sync(0xffffffffu, sc, o);
            if (lane >= o) sc += u;
        }
        int base = sc - s;
        off[2 * lane] = base;
        off[2 * lane + 1] = base + c0;
        if (lane == 31) s_nv = sc;
    }
    __syncthreads();
    #pragma unroll
    for (int s = 0; s < 4; s++) {
        int b = 4 * w + s;
        int o = off[b];
        #pragma unroll
        for (int ch = 0; ch < 4; ch++) {
            int pos = ch * 32 + lane;
            int flag = 0;
            if (pos <= LSEQ) flag = (pos == LSEQ) ? 1 : (log_mask[b * LSEQ + pos] != 0);
            unsigned bal = __ballot_sync(0xffffffffu, flag);
            if (flag)
                colid_s[o + __popc(bal & ((1u << lane) - 1u))] = b * LP1 + pos;
            o += __popc(bal);
        }
    }
    __syncthreads();
    return s_nv;
}

// Quick nv (for CTAs that don't need the column map).
__device__ __forceinline__ int local_nv(const int* __restrict__ log_mask) {
    __shared__ int acc[16];
    __shared__ int s_nv2;
    int t = threadIdx.x, w = t >> 5, lane = t & 31;
    int c = 0;
    for (int i = t; i < NROW; i += 512) c += (log_mask[i] != 0);
    #pragma unroll
    for (int o = 16; o > 0; o >>= 1) c += __shfl_down_sync(0xffffffffu, c, o);
    if (lane == 0) acc[w] = c;
    __syncthreads();
    if (t == 0) {
        int s = 0;
        #pragma unroll
        for (int i = 0; i < 16; i++) s += acc[i];
        s_nv2 = s + BSZ;
    }
    __syncthreads();
    return s_nv2;
}

// ---------------------------------------------------------------------------
// Megakernel: merged prep -> ONE gsync -> GEMM (4-deep ring, keep-in-accum,
// one sync per tile) -> distributed finalize.
// smem floats: A 4096 | B 4*4096 | K 4*384 | sred 512  = 22528 fl = 90112 B
// ---------------------------------------------------------------------------
#define SMEM_BYTES ((4096 + 4 * 4096 + 4 * 384 + 512) * 4)
#define HEMPTY 0xFFFFFFFFu

__global__ __launch_bounds__(512, 2)
void mega_kernel(const int* __restrict__ log_mask,
                 const int* __restrict__ items,
                 const float* __restrict__ pop,
                 const float* __restrict__ prec,
                 const float* __restrict__ embs,
                 float* __restrict__ out) {
    extern __shared__ float sm[];
    const int t = threadIdx.x;
    const int cta = blockIdx.y * gridDim.x + blockIdx.x;

    // ======================= Merged prep phase =======================
    int nv;
    if (cta < 116) {
        int* colid_s = (int*)sm;            // 6464 ints (26KB)
        nv = local_compact(log_mask, colid_s);
        if (cta < BSZ) {
            // ---- dup mask via 256-slot hash set; keep for batch `cta` ----
            __shared__ uint32_t tab[256];
            int i = cta;
            if (t < 256) tab[t] = HEMPTY;
            __syncthreads();
            if (t < LP1) {
                uint32_t id = (uint32_t)items[i * LP1 + t];
                uint32_t h = (id * 2654435761u) >> 24;
                while (true) {
                    uint32_t old = atomicCAS((unsigned int*)&tab[h], HEMPTY, id);
                    if (old == HEMPTY || old == id) break;
                    h = (h + 1) & 255;
                }
            }
            __syncthreads();
            int nvp = (nv + 127) & ~127;
            const float NINF = __int_as_float(0xff800000);
            for (int kv = t; kv < nvp; kv += 512) {
                float o = NINF;
                if (kv < nv) {
                    uint32_t id = (uint32_t)items[colid_s[kv]];
                    uint32_t h = (id * 2654435761u) >> 24;
                    bool dup = false;
                    while (true) {
                        uint32_t k = tab[h];
                        if (k == id) { dup = true; break; }
                        if (k == HEMPTY) break;
                        h = (h + 1) & 255;
                    }
                    o = dup ? NINF : -log2f(pop[id]);
                }
                g_keep[i * NCOLP + kv] = o;
            }
        } else {
            // ---- B fragments, one ktile per CTA: stage coalesced, pack ----
            int ktile = cta - BSZ;              // 0..51
            int kt128 = ktile * 128;
            float4* stage4 = (float4*)(sm + 8192);   // 32KB at byte 32768
            const float4* e4 = (const float4*)embs;
            const float4 z4 = make_float4(0.f, 0.f, 0.f, 0.f);
            #pragma unroll
            for (int it = 0; it < 4; it++) {
                int j = t + it * 512;            // 2048 float4s
                int col = j >> 4, q = j & 15;
                int gc = kt128 + col;
                stage4[j] = (gc < nv) ? e4[colid_s[gc] * 16 + q] : z4;
            }
            __syncthreads();
            const float* stage = (const float*)stage4;
            #pragma unroll
            for (int it = 0; it < 2; it++) {
                int j = t + it * 512;            // 1024 frag uint4s
                int lane = j & 31;
                int g = lane >> 2, tig = lane & 3;
                int kt = (j >> 5) & 3;
                int cc = (j >> 7) & 7;
                int k0 = kt * 16 + tig * 2;
                const float* e0 = stage + (cc * 16 + g) * 64;
                const float* e1 = e0 + 8 * 64;
                uint4 v;
                v.x = pk2(e0[k0], e0[k0 + 1]);
                v.y = pk2(e0[k0 + 8], e0[k0 + 9]);
                v.z = pk2(e1[k0], e1[k0 + 1]);
                v.w = pk2(e1[k0 + 8], e1[k0 + 9]);
                g_Bfrag4[ktile * 1024 + j] = v;
            }
        }
    } else if (cta < 166) {
        // ---- A fragments, one m-tile per CTA: stage coalesced, pack ----
        nv = local_nv(log_mask);
        int mt = cta - 116;                      // 0..49
        float4* stage4 = (float4*)(sm + 8192);
        const float4* p4 = (const float4*)prec;
        #pragma unroll
        for (int it = 0; it < 4; it++) {
            int j = t + it * 512;                // 2048 float4s, coalesced
            stage4[j] = p4[mt * 2048 + j];
        }
        __syncthreads();
        const float* stage = (const float*)stage4;
        #pragma unroll
        for (int it = 0; it < 2; it++) {
            int j = t + it * 512;
            int lane = j & 31;
            int g = lane >> 2, tig = lane & 3;
            int kt = (j >> 5) & 3;
            int b16 = (j >> 7) & 7;
            int k0 = kt * 16 + tig * 2;
            const float* ar = stage + (b16 * 16 + g) * 64;
            const float* ar8 = ar + 8 * 64;
            uint4 v;
            v.x = pk2(ar[k0] * LOG2E, ar[k0 + 1] * LOG2E);
            v.y = pk2(ar8[k0] * LOG2E, ar8[k0 + 1] * LOG2E);
            v.z = pk2(ar[k0 + 8] * LOG2E, ar[k0 + 9] * LOG2E);
            v.w = pk2(ar8[k0 + 8] * LOG2E, ar8[k0 + 9] * LOG2E);
            g_Afrag4[mt * 1024 + j] = v;
        }
    } else {
        // ---- target logits (exact fp32), 84 CTAs loop over 51200 slots ----
        nv = local_nv(log_mask);
        for (int slot = (cta - 166) * 512 + t; slot < NROW * 8; slot += 84 * 512) {
            int r = slot >> 3, sub = slot & 7;
            int i = r / LSEQ, j = r - i * LSEQ;
            int pos = j + 1;
            int valid = (pos == LSEQ) ? 1 : (log_mask[i * LSEQ + pos] != 0);
            int tc = i * LP1 + pos;
            const float4* p4 = (const float4*)(prec + r * DIM);
            const float4* e4 = (const float4*)(embs + tc * DIM);
            float4 a0 = p4[sub], b0 = e4[sub], a1 = p4[sub + 8], b1 = e4[sub + 8];
            float s = a0.x * b0.x + a0.y * b0.y + a0.z * b0.z + a0.w * b0.w
                    + a1.x * b1.x + a1.y * b1.y + a1.z * b1.z + a1.w * b1.w;
            s += __shfl_down_sync(0xffffffffu, s, 4);
            s += __shfl_down_sync(0xffffffffu, s, 2);
            s += __shfl_down_sync(0xffffffffu, s, 1);
            if (sub == 0) g_tgt[r] = valid ? (s - logf(pop[items[tc]])) : NEG10K;
        }
    }

    gsync(TOTAL_CTAS);

    // ======================= Phase C: GEMM + exp2 row-sums =======================
    uint4* As4 = (uint4*)sm;                                   // 16 KB
    uint4* Bs4[4] = {(uint4*)(sm + 4096), (uint4*)(sm + 8192),
                     (uint4*)(sm + 12288), (uint4*)(sm + 16384)};
    float* Ks[4] = {sm + 20480, sm + 20480 + 384, sm + 20480 + 768, sm + 20480 + 1152};
    float* sred = sm + 22016;                                  // [4][128]
    const uint32_t su = smem_u32(sm);
    const uint32_t Bu[4] = {su + 16384, su + 32768, su + 49152, su + 65536};
    const uint32_t Ku[4] = {su + 81920, su + 81920 + 1536,
                            su + 81920 + 3072, su + 81920 + 4608};

    const int w = t >> 5, lane = t & 31;
    const int g = lane >> 2, tig = lane & 3;
    const int rg = w >> 2;
    const int wcol = w & 3;
    const int m0 = blockIdx.x * 128;
    const int ch = blockIdx.y;
    const int T = (nv + 127) >> 7;
    const int ntiles = (T > ch) ? ((T - ch + NCH - 1) / NCH) : 0;
    const int bfirst = m0 / LSEQ;

    // keep-row offsets (element index into a 3*128 K tile) per mt/h
    int kb[2][2];
    #pragma unroll
    for (int mt = 0; mt < 2; mt++)
        #pragma unroll
        for (int h = 0; h < 2; h++)
            kb[mt][h] = ((m0 + rg * 32 + mt * 16 + g + h * 8) / LSEQ - bfirst) * 128
                      + wcol * 32 + 2 * tig;

    float rs[4] = {0.f, 0.f, 0.f, 0.f};

    if (ntiles > 0) {
        auto stageB = [&](int tile, int buf) {
            const uint4* Bg = g_Bfrag4 + (size_t)tile * 1024;
            cp16(Bu[buf] + t * 16, Bg + t);
            cp16(Bu[buf] + (t + 512) * 16, Bg + t + 512);
            if (t < 96) {
                int b = t >> 5, q = t & 31;
                int bg = min(bfirst + b, BSZ - 1);
                cp16(Ku[buf] + (b * 128 + q * 4) * 4,
                     g_keep + (size_t)bg * NCOLP + tile * 128 + q * 4);
            }
        };

        {
            const uint4* Ag = g_Afrag4 + (size_t)blockIdx.x * 1024;
            cp16(su + t * 16, Ag + t);
            cp16(su + (t + 512) * 16, Ag + t + 512);
        }
        stageB(ch, 0);
        CP_COMMIT();
        int committed = 1;
        if (ntiles > 1) { stageB(ch + NCH, 1); CP_COMMIT(); committed = 2; }
        if (ntiles > 2) { stageB(ch + 2 * NCH, 2); CP_COMMIT(); committed = 3; }

        const uint4* a0p = As4 + (rg * 2 + 0) * 128 + lane;
        const uint4* a1p = As4 + (rg * 2 + 1) * 128 + lane;

        for (int ti = 0; ti < ntiles; ti++) {
            int rem = committed - ti - 1;
            if (rem >= 2) CP_WAIT2(); else if (rem == 1) CP_WAIT1(); else CP_WAIT0();
            __syncthreads();   // data ready; also orders prior tile's readers
                               // before this tile's restage of the same slot

            int buf = ti & 3;
            const uint4* B4 = Bs4[buf];
            const float* KP = Ks[buf];

            #pragma unroll
            for (int cc2 = 0; cc2 < 2; cc2++) {
                const int cc = wcol * 2 + cc2;
                const uint4* bp = B4 + cc * 128 + lane;
                // init accumulators with keep terms (MMA adds on top; -inf
                // propagates through fp32 accumulation -> ex2 -> 0)
                float c[2][2][4];
                #pragma unroll
                for (int mt = 0; mt < 2; mt++) {
                    #pragma unroll
                    for (int nt = 0; nt < 2; nt++) {
                        int co = cc2 * 16 + nt * 8;
                        float2 k0 = *(const float2*)(KP + kb[mt][0] + co);
                        float2 k1 = *(const float2*)(KP + kb[mt][1] + co);
                        c[mt][nt][0] = k0.x; c[mt][nt][1] = k0.y;
                        c[mt][nt][2] = k1.x; c[mt][nt][3] = k1.y;
                    }
                }

                #pragma unroll
                for (int kt = 0; kt < 4; kt++) {
                    uint4 a0 = a0p[kt * 32];
                    uint4 a1 = a1p[kt * 32];
                    uint4 b = bp[kt * 32];
                    mma16(c[0][0], a0, b.x, b.y);
                    mma16(c[0][1], a0, b.z, b.w);
                    mma16(c[1][0], a1, b.x, b.y);
                    mma16(c[1][1], a1, b.z, b.w);
                }

                #pragma unroll
                for (int mt = 0; mt < 2; mt++) {
                    #pragma unroll
                    for (int nt = 0; nt < 2; nt++) {
                        rs[mt * 2 + 0] += ex2f(c[mt][nt][0]) + ex2f(c[mt][nt][1]);
                        rs[mt * 2 + 1] += ex2f(c[mt][nt][2]) + ex2f(c[mt][nt][3]);
                    }
                }
            }

            // stage tile ti+3 into slot (ti+3)&3 — last read at iteration
            // ti-1, ordered by this iteration's top __syncthreads.
            if (ti + 3 < ntiles) { stageB(ch + (ti + 3) * NCH, (ti + 3) & 3); CP_COMMIT(); committed++; }
        }
    }

    // in-CTA: reduce 4 tig lanes, then 4 col-group slices
    #pragma unroll
    for (int q = 0; q < 4; q++) {
        rs[q] += __shfl_xor_sync(0xffffffffu, rs[q], 1);
        rs[q] += __shfl_xor_sync(0xffffffffu, rs[q], 2);
    }
    __syncthreads();   // all warps done with B/K buffers before sred reuse path
    if (tig == 0) {
        #pragma unroll
        for (int mt = 0; mt < 2; mt++)
            #pragma unroll
            for (int h = 0; h < 2; h++)
                sred[wcol * 128 + rg * 32 + mt * 16 + h * 8 + g] = rs[mt * 2 + h];
    }
    __syncthreads();
    if (t < 128) {
        float s = (sred[t] + sred[t + 128]) + (sred[t + 256] + sred[t + 384]);
        g_partS[ch * NROW + m0 + t] = s;
    }

    // ============== Phase D: per-m-tile finalize + deterministic total ==============
    __shared__ unsigned int s_lastm;
    __threadfence();
    __syncthreads();
    if (t == 0)
        s_lastm = (atomicAdd(&g_mctr[blockIdx.x], 1u) == NCH - 1) ? 1u : 0u;
    __syncthreads();
    if (s_lastm) {
        __threadfence();
        double num = 0.0, den = 0.0;
        if (t < 128) {
            int r = m0 + t;
            float S = 0.f;
            #pragma unroll
            for (int c = 0; c < NCH; c++) S += g_partS[c * NROW + r];
            float tv = g_tgt[r];
            S += __expf(tv);
            float nll = (S > 0.f) ? (logf(S) - tv) : logf((float)NCOL);
            if (log_mask[r] != 0) { num = (double)nll; den = 1.0; }
        }
        #pragma unroll
        for (int o = 16; o > 0; o >>= 1) {
            num += __shfl_down_sync(0xffffffffu, num, o);
            den += __shfl_down_sync(0xffffffffu, den, o);
        }
        __shared__ double swn[16];
        __shared__ double swd[16];
        if (lane == 0) { swn[w] = num; swd[w] = den; }
        __syncthreads();
        if (t == 0) {
            double n = 0.0, d = 0.0;
            #pragma unroll
            for (int i = 0; i < 4; i++) { n += swn[i]; d += swd[i]; }
            g_rn[blockIdx.x] = n;
            g_rd[blockIdx.x] = d;
            __threadfence();
            if (atomicAdd(&g_fin, 1u) == 49u) {
                __threadfence();
                double tn = 0.0, td = 0.0;
                for (int i = 0; i < 50; i++) { tn += g_rn[i]; td += g_rd[i]; }
                out[0] = (float)(tn / td);
                // self-reset for next graph replay
                for (int i = 0; i < 50; i++) g_mctr[i] = 0u;
                g_fin = 0u;
                g_bar = 0u;
            }
        }
    }
}

// ---------------------------------------------------------------------------
extern "C" void kernel_launch(void* const* d_in, const int* in_sizes, int n_in,
                              void* d_out, int out_size) {
    const float* prec  = (const float*)d_in[0];  // [6400, 64]
    const float* embs  = (const float*)d_in[1];  // [6464, 64]
    const float* pop   = (const float*)d_in[2];  // [100001]
    const int*   items = (const int*)d_in[3];    // [6464]
    const int*   lmask = (const int*)d_in[4];    // [64, 100]
    float* out = (float*)d_out;

    cudaFuncSetAttribute(mega_kernel, cudaFuncAttributeMaxDynamicSharedMemorySize,
                         SMEM_BYTES);

    mega_kernel<<<dim3(50, NCH), 512, SMEM_BYTES>>>(lmask, items, pop, prec, embs, out);
}

// round 14
// speedup vs baseline: 1.0416x; 1.0416x over previous
#include <cuda_runtime.h>
#include <cuda_bf16.h>
#include <math.h>
#include <stdint.h>

// Problem constants
#define BSZ   64
#define LSEQ  100
#define LP1   101
#define DIM   64
#define NCOL  (BSZ * LP1)   // 6464
#define NROW  (BSZ * LSEQ)  // 6400
#define NCOLP 6656          // padded compacted-col bound (52 * 128)
#define NEG10K (-10000.0f)
#define LOG2E 1.4426950408889634f
#define NMT   50            // m-tiles
#define TOTAL_CTAS 296      // 148 SMs x 2 CTAs — every SM exactly 2, all resident
#define MAXP  6             // max worker CTAs per m-tile

// ---------------- scratch (__device__ globals; no allocs) ----------------
__device__ float  g_keep[BSZ * NCOLP];    // -log2(pop) or -inf per (batch, padded col)
__device__ uint4  g_Afrag4[NROW * 8];     // bf16(prec*log2e), m16n8k16 fragment order
__device__ uint4  g_Bfrag4[NCOLP * 8];    // bf16 compacted embs, fragment order
__device__ float  g_tgt[NROW];
__device__ float  g_partS[MAXP * NROW];   // [rank][row]
__device__ double g_rn[NMT];
__device__ double g_rd[NMT];
__device__ unsigned int g_bar;            // grid barrier counter (self-resetting)
__device__ unsigned int g_mctr[NMT];      // per-m-tile tickets (self-resetting)
__device__ unsigned int g_fin;            // finalizer ticket (self-resetting)

// ---------------- PTX helpers ----------------
__device__ __forceinline__ uint32_t smem_u32(const void* p) {
    uint32_t a;
    asm("{ .reg .u64 t; cvta.to.shared.u64 t, %1; cvt.u32.u64 %0, t; }" : "=r"(a) : "l"(p));
    return a;
}
__device__ __forceinline__ uint32_t pk2(float lo, float hi) {  // bf16x2, RN (unbiased)
    __nv_bfloat162 h = __floats2bfloat162_rn(lo, hi);
    return *(uint32_t*)&h;
}
__device__ __forceinline__ float ex2f(float x) {               // 2^x, -inf -> 0
    float y;
    asm("ex2.approx.f32 %0, %1;" : "=f"(y) : "f"(x));
    return y;
}
__device__ __forceinline__ void cp16(uint32_t dst, const void* src) {
    asm volatile("cp.async.ca.shared.global [%0], [%1], 16;" :: "r"(dst), "l"(src) : "memory");
}
#define CP_COMMIT()  asm volatile("cp.async.commit_group;" ::: "memory")
#define CP_WAIT0()   asm volatile("cp.async.wait_group 0;" ::: "memory")
#define CP_WAIT1()   asm volatile("cp.async.wait_group 1;" ::: "memory")
#define CP_WAIT2()   asm volatile("cp.async.wait_group 2;" ::: "memory")

__device__ __forceinline__ void mma16(float* c, uint4 a, uint32_t b0, uint32_t b1) {
    asm volatile("mma.sync.aligned.m16n8k16.row.col.f32.bf16.bf16.f32 "
        "{%0,%1,%2,%3}, {%4,%5,%6,%7}, {%8,%9}, {%0,%1,%2,%3};"
        : "+f"(c[0]), "+f"(c[1]), "+f"(c[2]), "+f"(c[3])
        : "r"(a.x), "r"(a.y), "r"(a.z), "r"(a.w), "r"(b0), "r"(b1));
}

// Grid-wide barrier (all 296 CTAs resident by construction).
__device__ __forceinline__ void gsync(unsigned int target) {
    __threadfence();
    __syncthreads();
    if (threadIdx.x == 0) {
        atomicAdd(&g_bar, 1u);
        while (*(volatile unsigned int*)&g_bar < target) { __nanosleep(32); }
    }
    __syncthreads();
}

// Local (per-CTA) compacted-column map into smem; returns nv. 512 threads.
__device__ __forceinline__ int local_compact(const int* __restrict__ log_mask,
                                             int* colid_s) {
    __shared__ int cnt[64];
    __shared__ int off[64];
    __shared__ int s_nv;
    int t = threadIdx.x, w = t >> 5, lane = t & 31;
    #pragma unroll
    for (int s = 0; s < 4; s++) {
        int b = 4 * w + s;
        int c = 0;
        #pragma unroll
        for (int ch = 0; ch < 4; ch++) {
            int pos = ch * 32 + lane;
            int flag = 0;
            if (pos <= LSEQ) flag = (pos == LSEQ) ? 1 : (log_mask[b * LSEQ + pos] != 0);
            c += __popc(__ballot_sync(0xffffffffu, flag));
        }
        if (lane == 0) cnt[b] = c;
    }
    __syncthreads();
    if (w == 0) {
        int c0 = cnt[2 * lane], c1 = cnt[2 * lane + 1];
        int s = c0 + c1, sc = s;
        #pragma unroll
        for (int o = 1; o < 32; o <<= 1) {
            int u = __shfl_up_sync(0xffffffffu, sc, o);
            if (lane >= o) sc += u;
        }
        int base = sc - s;
        off[2 * lane] = base;
        off[2 * lane + 1] = base + c0;
        if (lane == 31) s_nv = sc;
    }
    __syncthreads();
    #pragma unroll
    for (int s = 0; s < 4; s++) {
        int b = 4 * w + s;
        int o = off[b];
        #pragma unroll
        for (int ch = 0; ch < 4; ch++) {
            int pos = ch * 32 + lane;
            int flag = 0;
            if (pos <= LSEQ) flag = (pos == LSEQ) ? 1 : (log_mask[b * LSEQ + pos] != 0);
            unsigned bal = __ballot_sync(0xffffffffu, flag);
            if (flag)
                colid_s[o + __popc(bal & ((1u << lane) - 1u))] = b * LP1 + pos;
            o += __popc(bal);
        }
    }
    __syncthreads();
    return s_nv;
}

// Quick nv (for CTAs that don't need the column map).
__device__ __forceinline__ int local_nv(const int* __restrict__ log_mask) {
    __shared__ int acc[16];
    __shared__ int s_nv2;
    int t = threadIdx.x, w = t >> 5, lane = t & 31;
    int c = 0;
    for (int i = t; i < NROW; i += 512) c += (log_mask[i] != 0);
    #pragma unroll
    for (int o = 16; o > 0; o >>= 1) c += __shfl_down_sync(0xffffffffu, c, o);
    if (lane == 0) acc[w] = c;
    __syncthreads();
    if (t == 0) {
        int s = 0;
        #pragma unroll
        for (int i = 0; i < 16; i++) s += acc[i];
        s_nv2 = s + BSZ;
    }
    __syncthreads();
    return s_nv2;
}

// ---------------------------------------------------------------------------
// Megakernel: merged prep -> ONE gsync -> balanced GEMM (296 CTAs, 2/SM
// everywhere) -> distributed finalize.
// smem floats: A 4096 | B 4*4096 | K 4*384 | sred 512  = 22528 fl = 90112 B
// ---------------------------------------------------------------------------
#define SMEM_BYTES ((4096 + 4 * 4096 + 4 * 384 + 512) * 4)
#define HEMPTY 0xFFFFFFFFu

__global__ __launch_bounds__(512, 2)
void mega_kernel(const int* __restrict__ log_mask,
                 const int* __restrict__ items,
                 const float* __restrict__ pop,
                 const float* __restrict__ prec,
                 const float* __restrict__ embs,
                 float* __restrict__ out) {
    extern __shared__ float sm[];
    const int t = threadIdx.x;
    const int cta = blockIdx.x;

    // ======================= Merged prep phase =======================
    int nv;
    if (cta < 116) {
        int* colid_s = (int*)sm;            // 6464 ints (26KB)
        nv = local_compact(log_mask, colid_s);
        if (cta < BSZ) {
            // ---- dup mask via 256-slot hash set; keep for batch `cta` ----
            __shared__ uint32_t tab[256];
            int i = cta;
            if (t < 256) tab[t] = HEMPTY;
            __syncthreads();
            if (t < LP1) {
                uint32_t id = (uint32_t)items[i * LP1 + t];
                uint32_t h = (id * 2654435761u) >> 24;
                while (true) {
                    uint32_t old = atomicCAS((unsigned int*)&tab[h], HEMPTY, id);
                    if (old == HEMPTY || old == id) break;
                    h = (h + 1) & 255;
                }
            }
            __syncthreads();
            int nvp = (nv + 127) & ~127;
            const float NINF = __int_as_float(0xff800000);
            for (int kv = t; kv < nvp; kv += 512) {
                float o = NINF;
                if (kv < nv) {
                    uint32_t id = (uint32_t)items[colid_s[kv]];
                    uint32_t h = (id * 2654435761u) >> 24;
                    bool dup = false;
                    while (true) {
                        uint32_t k = tab[h];
                        if (k == id) { dup = true; break; }
                        if (k == HEMPTY) break;
                        h = (h + 1) & 255;
                    }
                    o = dup ? NINF : -log2f(pop[id]);
                }
                g_keep[i * NCOLP + kv] = o;
            }
        } else {
            // ---- B fragments, one ktile per CTA: stage coalesced, pack ----
            int ktile = cta - BSZ;              // 0..51
            int kt128 = ktile * 128;
            float4* stage4 = (float4*)(sm + 8192);   // 32KB at byte 32768
            const float4* e4 = (const float4*)embs;
            const float4 z4 = make_float4(0.f, 0.f, 0.f, 0.f);
            #pragma unroll
            for (int it = 0; it < 4; it++) {
                int j = t + it * 512;            // 2048 float4s
                int col = j >> 4, q = j & 15;
                int gc = kt128 + col;
                stage4[j] = (gc < nv) ? e4[colid_s[gc] * 16 + q] : z4;
            }
            __syncthreads();
            const float* stage = (const float*)stage4;
            #pragma unroll
            for (int it = 0; it < 2; it++) {
                int j = t + it * 512;            // 1024 frag uint4s
                int lane = j & 31;
                int g = lane >> 2, tig = lane & 3;
                int kt = (j >> 5) & 3;
                int cc = (j >> 7) & 7;
                int k0 = kt * 16 + tig * 2;
                const float* e0 = stage + (cc * 16 + g) * 64;
                const float* e1 = e0 + 8 * 64;
                uint4 v;
                v.x = pk2(e0[k0], e0[k0 + 1]);
                v.y = pk2(e0[k0 + 8], e0[k0 + 9]);
                v.z = pk2(e1[k0], e1[k0 + 1]);
                v.w = pk2(e1[k0 + 8], e1[k0 + 9]);
                g_Bfrag4[ktile * 1024 + j] = v;
            }
        }
    } else if (cta < 166) {
        // ---- A fragments, one m-tile per CTA: stage coalesced, pack ----
        nv = local_nv(log_mask);
        int mt = cta - 116;                      // 0..49
        float4* stage4 = (float4*)(sm + 8192);
        const float4* p4 = (const float4*)prec;
        #pragma unroll
        for (int it = 0; it < 4; it++) {
            int j = t + it * 512;                // 2048 float4s, coalesced
            stage4[j] = p4[mt * 2048 + j];
        }
        __syncthreads();
        const float* stage = (const float*)stage4;
        #pragma unroll
        for (int it = 0; it < 2; it++) {
            int j = t + it * 512;
            int lane = j & 31;
            int g = lane >> 2, tig = lane & 3;
            int kt = (j >> 5) & 3;
            int b16 = (j >> 7) & 7;
            int k0 = kt * 16 + tig * 2;
            const float* ar = stage + (b16 * 16 + g) * 64;
            const float* ar8 = ar + 8 * 64;
            uint4 v;
            v.x = pk2(ar[k0] * LOG2E, ar[k0 + 1] * LOG2E);
            v.y = pk2(ar8[k0] * LOG2E, ar8[k0 + 1] * LOG2E);
            v.z = pk2(ar[k0 + 8] * LOG2E, ar[k0 + 9] * LOG2E);
            v.w = pk2(ar8[k0 + 8] * LOG2E, ar8[k0 + 9] * LOG2E);
            g_Afrag4[mt * 1024 + j] = v;
        }
    } else {
        // ---- target logits (exact fp32), 130 CTAs over 51200 slots ----
        nv = local_nv(log_mask);
        for (int slot = (cta - 166) * 512 + t; slot < NROW * 8; slot += 130 * 512) {
            int r = slot >> 3, sub = slot & 7;
            int i = r / LSEQ, j = r - i * LSEQ;
            int pos = j + 1;
            int valid = (pos == LSEQ) ? 1 : (log_mask[i * LSEQ + pos] != 0);
            int tc = i * LP1 + pos;
            const float4* p4 = (const float4*)(prec + r * DIM);
            const float4* e4 = (const float4*)(embs + tc * DIM);
            float4 a0 = p4[sub], b0 = e4[sub], a1 = p4[sub + 8], b1 = e4[sub + 8];
            float s = a0.x * b0.x + a0.y * b0.y + a0.z * b0.z + a0.w * b0.w
                    + a1.x * b1.x + a1.y * b1.y + a1.z * b1.z + a1.w * b1.w;
            s += __shfl_down_sync(0xffffffffu, s, 4);
            s += __shfl_down_sync(0xffffffffu, s, 2);
            s += __shfl_down_sync(0xffffffffu, s, 1);
            if (sub == 0) g_tgt[r] = valid ? (s - logf(pop[items[tc]])) : NEG10K;
        }
    }

    gsync(TOTAL_CTAS);

    // ======================= Phase C: GEMM + exp2 row-sums =======================
    // Balanced decomposition: mt = cta % 50, rank r = cta / 50.
    // m-tiles 0..45 have P=6 worker CTAs; 46..49 have P=5.
    uint4* As4 = (uint4*)sm;                                   // 16 KB
    uint4* Bs4[4] = {(uint4*)(sm + 4096), (uint4*)(sm + 8192),
                     (uint4*)(sm + 12288), (uint4*)(sm + 16384)};
    float* Ks[4] = {sm + 20480, sm + 20480 + 384, sm + 20480 + 768, sm + 20480 + 1152};
    float* sred = sm + 22016;                                  // [4][128]
    const uint32_t su = smem_u32(sm);
    const uint32_t Bu[4] = {su + 16384, su + 32768, su + 49152, su + 65536};
    const uint32_t Ku[4] = {su + 81920, su + 81920 + 1536,
                            su + 81920 + 3072, su + 81920 + 4608};

    const int w = t >> 5, lane = t & 31;
    const int g = lane >> 2, tig = lane & 3;
    const int rg = w >> 2;
    const int wcol = w & 3;
    const int mt_ = cta % NMT;
    const int rnk = cta / NMT;                 // 0..5
    const int P = (mt_ < 46) ? 6 : 5;
    const int m0 = mt_ * 128;
    const int T = (nv + 127) >> 7;
    const int ntiles = (T > rnk) ? ((T - rnk + P - 1) / P) : 0;
    const int bfirst = m0 / LSEQ;

    // keep-row offsets (element index into a 3*128 K tile) per mtile/h
    int kb[2][2];
    #pragma unroll
    for (int mti = 0; mti < 2; mti++)
        #pragma unroll
        for (int h = 0; h < 2; h++)
            kb[mti][h] = ((m0 + rg * 32 + mti * 16 + g + h * 8) / LSEQ - bfirst) * 128
                       + wcol * 32 + 2 * tig;

    float rs[4] = {0.f, 0.f, 0.f, 0.f};

    if (ntiles > 0) {
        auto stageB = [&](int tile, int buf) {
            const uint4* Bg = g_Bfrag4 + (size_t)tile * 1024;
            cp16(Bu[buf] + t * 16, Bg + t);
            cp16(Bu[buf] + (t + 512) * 16, Bg + t + 512);
            if (t < 96) {
                int b = t >> 5, q = t & 31;
                int bg = min(bfirst + b, BSZ - 1);
                cp16(Ku[buf] + (b * 128 + q * 4) * 4,
                     g_keep + (size_t)bg * NCOLP + tile * 128 + q * 4);
            }
        };

        {
            const uint4* Ag = g_Afrag4 + (size_t)mt_ * 1024;
            cp16(su + t * 16, Ag + t);
            cp16(su + (t + 512) * 16, Ag + t + 512);
        }
        stageB(rnk, 0);
        CP_COMMIT();
        int committed = 1;
        if (ntiles > 1) { stageB(rnk + P, 1); CP_COMMIT(); committed = 2; }
        if (ntiles > 2) { stageB(rnk + 2 * P, 2); CP_COMMIT(); committed = 3; }

        const uint4* a0p = As4 + (rg * 2 + 0) * 128 + lane;
        const uint4* a1p = As4 + (rg * 2 + 1) * 128 + lane;

        for (int ti = 0; ti < ntiles; ti++) {
            int rem = committed - ti - 1;
            if (rem >= 2) CP_WAIT2(); else if (rem == 1) CP_WAIT1(); else CP_WAIT0();
            __syncthreads();   // data ready; also orders prior tile's readers
                               // before this tile's restage of the same slot

            int buf = ti & 3;
            const uint4* B4 = Bs4[buf];
            const float* KP = Ks[buf];

            #pragma unroll
            for (int cc2 = 0; cc2 < 2; cc2++) {
                const int cc = wcol * 2 + cc2;
                const uint4* bp = B4 + cc * 128 + lane;
                // init accumulators with keep terms (-inf propagates -> ex2 -> 0)
                float c[2][2][4];
                #pragma unroll
                for (int mti = 0; mti < 2; mti++) {
                    #pragma unroll
                    for (int nt = 0; nt < 2; nt++) {
                        int co = cc2 * 16 + nt * 8;
                        float2 k0 = *(const float2*)(KP + kb[mti][0] + co);
                        float2 k1 = *(const float2*)(KP + kb[mti][1] + co);
                        c[mti][nt][0] = k0.x; c[mti][nt][1] = k0.y;
                        c[mti][nt][2] = k1.x; c[mti][nt][3] = k1.y;
                    }
                }

                #pragma unroll
                for (int kt = 0; kt < 4; kt++) {
                    uint4 a0 = a0p[kt * 32];
                    uint4 a1 = a1p[kt * 32];
                    uint4 b = bp[kt * 32];
                    mma16(c[0][0], a0, b.x, b.y);
                    mma16(c[0][1], a0, b.z, b.w);
                    mma16(c[1][0], a1, b.x, b.y);
                    mma16(c[1][1], a1, b.z, b.w);
                }

                #pragma unroll
                for (int mti = 0; mti < 2; mti++) {
                    #pragma unroll
                    for (int nt = 0; nt < 2; nt++) {
                        rs[mti * 2 + 0] += ex2f(c[mti][nt][0]) + ex2f(c[mti][nt][1]);
                        rs[mti * 2 + 1] += ex2f(c[mti][nt][2]) + ex2f(c[mti][nt][3]);
                    }
                }
            }

            if (ti + 3 < ntiles) { stageB(rnk + (ti + 3) * P, (ti + 3) & 3); CP_COMMIT(); committed++; }
        }
    }

    // in-CTA: reduce 4 tig lanes, then 4 col-group slices
    #pragma unroll
    for (int q = 0; q < 4; q++) {
        rs[q] += __shfl_xor_sync(0xffffffffu, rs[q], 1);
        rs[q] += __shfl_xor_sync(0xffffffffu, rs[q], 2);
    }
    __syncthreads();   // all warps done with B/K buffers before sred reuse
    if (tig == 0) {
        #pragma unroll
        for (int mti = 0; mti < 2; mti++)
            #pragma unroll
            for (int h = 0; h < 2; h++)
                sred[wcol * 128 + rg * 32 + mti * 16 + h * 8 + g] = rs[mti * 2 + h];
    }
    __syncthreads();
    if (t < 128) {
        float s = (sred[t] + sred[t + 128]) + (sred[t + 256] + sred[t + 384]);
        g_partS[rnk * NROW + m0 + t] = s;
    }

    // ============== Phase D: per-m-tile finalize + deterministic total ==============
    __shared__ unsigned int s_lastm;
    __threadfence();
    __syncthreads();
    if (t == 0)
        s_lastm = (atomicAdd(&g_mctr[mt_], 1u) == (unsigned)(P - 1)) ? 1u : 0u;
    __syncthreads();
    if (s_lastm) {
        __threadfence();
        double num = 0.0, den = 0.0;
        if (t < 128) {
            int r = m0 + t;
            float S = 0.f;
            for (int c = 0; c < P; c++) S += g_partS[c * NROW + r];
            float tv = g_tgt[r];
            S += __expf(tv);
            float nll = (S > 0.f) ? (logf(S) - tv) : logf((float)NCOL);
            if (log_mask[r] != 0) { num = (double)nll; den = 1.0; }
        }
        #pragma unroll
        for (int o = 16; o > 0; o >>= 1) {
            num += __shfl_down_sync(0xffffffffu, num, o);
            den += __shfl_down_sync(0xffffffffu, den, o);
        }
        __shared__ double swn[16];
        __shared__ double swd[16];
        if (lane == 0) { swn[w] = num; swd[w] = den; }
        __syncthreads();
        if (t == 0) {
            double n = 0.0, d = 0.0;
            #pragma unroll
            for (int i = 0; i < 4; i++) { n += swn[i]; d += swd[i]; }
            g_rn[mt_] = n;
            g_rd[mt_] = d;
            __threadfence();
            if (atomicAdd(&g_fin, 1u) == NMT - 1) {
                __threadfence();
                double tn = 0.0, td = 0.0;
                for (int i = 0; i < NMT; i++) { tn += g_rn[i]; td += g_rd[i]; }
                out[0] = (float)(tn / td);
                // self-reset for next graph replay
                for (int i = 0; i < NMT; i++) g_mctr[i] = 0u;
                g_fin = 0u;
                g_bar = 0u;
            }
        }
    }
}

// ---------------------------------------------------------------------------
extern "C" void kernel_launch(void* const* d_in, const int* in_sizes, int n_in,
                              void* d_out, int out_size) {
    const float* prec  = (const float*)d_in[0];  // [6400, 64]
    const float* embs  = (const float*)d_in[1];  // [6464, 64]
    const float* pop   = (const float*)d_in[2];  // [100001]
    const int*   items = (const int*)d_in[3];    // [6464]
    const int*   lmask = (const int*)d_in[4];    // [64, 100]
    float* out = (float*)d_out;

    cudaFuncSetAttribute(mega_kernel, cudaFuncAttributeMaxDynamicSharedMemorySize,
                         SMEM_BYTES);

    mega_kernel<<<TOTAL_CTAS, 512, SMEM_BYTES>>>(lmask, items, pop, prec, embs, out);
}

// round 15
// speedup vs baseline: 1.1811x; 1.1340x over previous
#include <cuda_runtime.h>
#include <cuda_bf16.h>
#include <math.h>
#include <stdint.h>

// Problem constants
#define BSZ   64
#define LSEQ  100
#define LP1   101
#define DIM   64
#define NCOL  (BSZ * LP1)   // 6464
#define NROW  (BSZ * LSEQ)  // 6400
#define NCOLP 6656          // padded compacted-col bound (52 * 128)
#define NEG10K (-10000.0f)
#define LOG2E 1.4426950408889634f
#define NMT   50            // m-tiles
#define TOTAL_CTAS 296      // 148 SMs x 2 CTAs — every SM exactly 2, all resident
#define MAXP  6             // max worker CTAs per m-tile

// ---------------- scratch (__device__ globals; no allocs) ----------------
__device__ float  g_keep[BSZ * NCOLP];    // -log2(pop) or -inf per (batch, padded col)
__device__ uint4  g_Afrag4[NROW * 8];     // bf16(prec*log2e), m16n8k16 fragment order
__device__ uint4  g_Bfrag4[NCOLP * 8];    // bf16 compacted embs, fragment order
__device__ float  g_tgt[NROW];
__device__ float  g_partS[MAXP * NROW];   // [rank][row]
__device__ double g_rn[NMT];
__device__ double g_rd[NMT];
__device__ unsigned int g_bar;            // grid barrier counter (self-resetting)
__device__ unsigned int g_mctr[NMT];      // per-m-tile tickets (self-resetting)
__device__ unsigned int g_fin;            // finalizer ticket (self-resetting)

// ---------------- PTX helpers ----------------
__device__ __forceinline__ uint32_t smem_u32(const void* p) {
    uint32_t a;
    asm("{ .reg .u64 t; cvta.to.shared.u64 t, %1; cvt.u32.u64 %0, t; }" : "=r"(a) : "l"(p));
    return a;
}
__device__ __forceinline__ uint32_t pk2(float lo, float hi) {  // bf16x2, RN (unbiased)
    __nv_bfloat162 h = __floats2bfloat162_rn(lo, hi);
    return *(uint32_t*)&h;
}
__device__ __forceinline__ float ex2f(float x) {               // 2^x, -inf -> 0
    float y;
    asm("ex2.approx.f32 %0, %1;" : "=f"(y) : "f"(x));
    return y;
}
__device__ __forceinline__ void cp16(uint32_t dst, const void* src) {
    asm volatile("cp.async.ca.shared.global [%0], [%1], 16;" :: "r"(dst), "l"(src) : "memory");
}
#define CP_COMMIT()  asm volatile("cp.async.commit_group;" ::: "memory")
#define CP_WAIT0()   asm volatile("cp.async.wait_group 0;" ::: "memory")

__device__ __forceinline__ void mma16(float* c, uint4 a, uint32_t b0, uint32_t b1) {
    asm volatile("mma.sync.aligned.m16n8k16.row.col.f32.bf16.bf16.f32 "
        "{%0,%1,%2,%3}, {%4,%5,%6,%7}, {%8,%9}, {%0,%1,%2,%3};"
        : "+f"(c[0]), "+f"(c[1]), "+f"(c[2]), "+f"(c[3])
        : "r"(a.x), "r"(a.y), "r"(a.z), "r"(a.w), "r"(b0), "r"(b1));
}

// Grid-wide barrier (all 296 CTAs resident by construction).
__device__ __forceinline__ void gsync(unsigned int target) {
    __threadfence();
    __syncthreads();
    if (threadIdx.x == 0) {
        atomicAdd(&g_bar, 1u);
        while (*(volatile unsigned int*)&g_bar < target) { __nanosleep(32); }
    }
    __syncthreads();
}

// Local (per-CTA) compacted-column map into smem; returns nv. 512 threads.
__device__ __forceinline__ int local_compact(const int* __restrict__ log_mask,
                                             int* colid_s) {
    __shared__ int cnt[64];
    __shared__ int off[64];
    __shared__ int s_nv;
    int t = threadIdx.x, w = t >> 5, lane = t & 31;
    #pragma unroll
    for (int s = 0; s < 4; s++) {
        int b = 4 * w + s;
        int c = 0;
        #pragma unroll
        for (int ch = 0; ch < 4; ch++) {
            int pos = ch * 32 + lane;
            int flag = 0;
            if (pos <= LSEQ) flag = (pos == LSEQ) ? 1 : (log_mask[b * LSEQ + pos] != 0);
            c += __popc(__ballot_sync(0xffffffffu, flag));
        }
        if (lane == 0) cnt[b] = c;
    }
    __syncthreads();
    if (w == 0) {
        int c0 = cnt[2 * lane], c1 = cnt[2 * lane + 1];
        int s = c0 + c1, sc = s;
        #pragma unroll
        for (int o = 1; o < 32; o <<= 1) {
            int u = __shfl_up_sync(0xffffffffu, sc, o);
            if (lane >= o) sc += u;
        }
        int base = sc - s;
        off[2 * lane] = base;
        off[2 * lane + 1] = base + c0;
        if (lane == 31) s_nv = sc;
    }
    __syncthreads();
    #pragma unroll
    for (int s = 0; s < 4; s++) {
        int b = 4 * w + s;
        int o = off[b];
        #pragma unroll
        for (int ch = 0; ch < 4; ch++) {
            int pos = ch * 32 + lane;
            int flag = 0;
            if (pos <= LSEQ) flag = (pos == LSEQ) ? 1 : (log_mask[b * LSEQ + pos] != 0);
            unsigned bal = __ballot_sync(0xffffffffu, flag);
            if (flag)
                colid_s[o + __popc(bal & ((1u << lane) - 1u))] = b * LP1 + pos;
            o += __popc(bal);
        }
    }
    __syncthreads();
    return s_nv;
}

// Quick nv (for CTAs that don't need the column map).
__device__ __forceinline__ int local_nv(const int* __restrict__ log_mask) {
    __shared__ int acc[16];
    __shared__ int s_nv2;
    int t = threadIdx.x, w = t >> 5, lane = t & 31;
    int c = 0;
    for (int i = t; i < NROW; i += 512) c += (log_mask[i] != 0);
    #pragma unroll
    for (int o = 16; o > 0; o >>= 1) c += __shfl_down_sync(0xffffffffu, c, o);
    if (lane == 0) acc[w] = c;
    __syncthreads();
    if (t == 0) {
        int s = 0;
        #pragma unroll
        for (int i = 0; i < 16; i++) s += acc[i];
        s_nv2 = s + BSZ;
    }
    __syncthreads();
    return s_nv2;
}

// ---------------------------------------------------------------------------
// Megakernel: merged prep -> ONE gsync -> sync-free GEMM (B + keep straight
// from L2, A in smem) -> distributed finalize.
// smem: prep needs colid (26KB) + stage at byte 32768 (32KB) -> 64KB + pad.
// ---------------------------------------------------------------------------
#define SMEM_BYTES 66560
#define HEMPTY 0xFFFFFFFFu

__global__ __launch_bounds__(512, 2)
void mega_kernel(const int* __restrict__ log_mask,
                 const int* __restrict__ items,
                 const float* __restrict__ pop,
                 const float* __restrict__ prec,
                 const float* __restrict__ embs,
                 float* __restrict__ out) {
    extern __shared__ float sm[];
    const int t = threadIdx.x;
    const int cta = blockIdx.x;

    // ======================= Merged prep phase =======================
    int nv;
    if (cta < 116) {
        int* colid_s = (int*)sm;            // 6464 ints (26KB)
        nv = local_compact(log_mask, colid_s);
        if (cta < BSZ) {
            // ---- dup mask via 256-slot hash set; keep for batch `cta` ----
            __shared__ uint32_t tab[256];
            int i = cta;
            if (t < 256) tab[t] = HEMPTY;
            __syncthreads();
            if (t < LP1) {
                uint32_t id = (uint32_t)items[i * LP1 + t];
                uint32_t h = (id * 2654435761u) >> 24;
                while (true) {
                    uint32_t old = atomicCAS((unsigned int*)&tab[h], HEMPTY, id);
                    if (old == HEMPTY || old == id) break;
                    h = (h + 1) & 255;
                }
            }
            __syncthreads();
            int nvp = (nv + 127) & ~127;
            const float NINF = __int_as_float(0xff800000);
            for (int kv = t; kv < nvp; kv += 512) {
                float o = NINF;
                if (kv < nv) {
                    uint32_t id = (uint32_t)items[colid_s[kv]];
                    uint32_t h = (id * 2654435761u) >> 24;
                    bool dup = false;
                    while (true) {
                        uint32_t k = tab[h];
                        if (k == id) { dup = true; break; }
                        if (k == HEMPTY) break;
                        h = (h + 1) & 255;
                    }
                    o = dup ? NINF : -log2f(pop[id]);
                }
                g_keep[i * NCOLP + kv] = o;
            }
        } else {
            // ---- B fragments, one ktile per CTA: stage coalesced, pack ----
            int ktile = cta - BSZ;              // 0..51
            int kt128 = ktile * 128;
            float4* stage4 = (float4*)(sm + 8192);   // 32KB at byte 32768
            const float4* e4 = (const float4*)embs;
            const float4 z4 = make_float4(0.f, 0.f, 0.f, 0.f);
            #pragma unroll
            for (int it = 0; it < 4; it++) {
                int j = t + it * 512;            // 2048 float4s
                int col = j >> 4, q = j & 15;
                int gc = kt128 + col;
                stage4[j] = (gc < nv) ? e4[colid_s[gc] * 16 + q] : z4;
            }
            __syncthreads();
            const float* stage = (const float*)stage4;
            #pragma unroll
            for (int it = 0; it < 2; it++) {
                int j = t + it * 512;            // 1024 frag uint4s
                int lane = j & 31;
                int g = lane >> 2, tig = lane & 3;
                int kt = (j >> 5) & 3;
                int cc = (j >> 7) & 7;
                int k0 = kt * 16 + tig * 2;
                const float* e0 = stage + (cc * 16 + g) * 64;
                const float* e1 = e0 + 8 * 64;
                uint4 v;
                v.x = pk2(e0[k0], e0[k0 + 1]);
                v.y = pk2(e0[k0 + 8], e0[k0 + 9]);
                v.z = pk2(e1[k0], e1[k0 + 1]);
                v.w = pk2(e1[k0 + 8], e1[k0 + 9]);
                g_Bfrag4[ktile * 1024 + j] = v;
            }
        }
    } else if (cta < 166) {
        // ---- A fragments, one m-tile per CTA: stage coalesced, pack ----
        nv = local_nv(log_mask);
        int mt = cta - 116;                      // 0..49
        float4* stage4 = (float4*)(sm + 8192);
        const float4* p4 = (const float4*)prec;
        #pragma unroll
        for (int it = 0; it < 4; it++) {
            int j = t + it * 512;                // 2048 float4s, coalesced
            stage4[j] = p4[mt * 2048 + j];
        }
        __syncthreads();
        const float* stage = (const float*)stage4;
        #pragma unroll
        for (int it = 0; it < 2; it++) {
            int j = t + it * 512;
            int lane = j & 31;
            int g = lane >> 2, tig = lane & 3;
            int kt = (j >> 5) & 3;
            int b16 = (j >> 7) & 7;
            int k0 = kt * 16 + tig * 2;
            const float* ar = stage + (b16 * 16 + g) * 64;
            const float* ar8 = ar + 8 * 64;
            uint4 v;
            v.x = pk2(ar[k0] * LOG2E, ar[k0 + 1] * LOG2E);
            v.y = pk2(ar8[k0] * LOG2E, ar8[k0 + 1] * LOG2E);
            v.z = pk2(ar[k0 + 8] * LOG2E, ar[k0 + 9] * LOG2E);
            v.w = pk2(ar8[k0 + 8] * LOG2E, ar8[k0 + 9] * LOG2E);
            g_Afrag4[mt * 1024 + j] = v;
        }
    } else {
        // ---- target logits (exact fp32), 130 CTAs over 51200 slots ----
        nv = local_nv(log_mask);
        for (int slot = (cta - 166) * 512 + t; slot < NROW * 8; slot += 130 * 512) {
            int r = slot >> 3, sub = slot & 7;
            int i = r / LSEQ, j = r - i * LSEQ;
            int pos = j + 1;
            int valid = (pos == LSEQ) ? 1 : (log_mask[i * LSEQ + pos] != 0);
            int tc = i * LP1 + pos;
            const float4* p4 = (const float4*)(prec + r * DIM);
            const float4* e4 = (const float4*)(embs + tc * DIM);
            float4 a0 = p4[sub], b0 = e4[sub], a1 = p4[sub + 8], b1 = e4[sub + 8];
            float s = a0.x * b0.x + a0.y * b0.y + a0.z * b0.z + a0.w * b0.w
                    + a1.x * b1.x + a1.y * b1.y + a1.z * b1.z + a1.w * b1.w;
            s += __shfl_down_sync(0xffffffffu, s, 4);
            s += __shfl_down_sync(0xffffffffu, s, 2);
            s += __shfl_down_sync(0xffffffffu, s, 1);
            if (sub == 0) g_tgt[r] = valid ? (s - logf(pop[items[tc]])) : NEG10K;
        }
    }

    gsync(TOTAL_CTAS);

    // ======================= Phase C: sync-free GEMM + exp2 row-sums ==========
    // mt = cta % 50, rank = cta / 50; m-tiles 0..45: P=6 workers, 46..49: P=5.
    // A resident in smem (staged once); B fragments + keep terms read straight
    // from L2 (__ldg). Zero __syncthreads inside the tile loop.
    uint4* As4 = (uint4*)sm;                                   // 16 KB
    float* sred = sm + 4096;                                   // [4][128]

    const int w = t >> 5, lane = t & 31;
    const int g = lane >> 2, tig = lane & 3;
    const int rg = w >> 2;
    const int wcol = w & 3;
    const int mt_ = cta % NMT;
    const int rnk = cta / NMT;                 // 0..5
    const int P = (mt_ < 46) ? 6 : 5;
    const int m0 = mt_ * 128;
    const int T = (nv + 127) >> 7;
    const int ntiles = (T > rnk) ? ((T - rnk + P - 1) / P) : 0;
    const int bfirst = m0 / LSEQ;

    // per-(mti,h) keep base pointers: batch row + column-group offset
    const float* kgp[2][2];
    #pragma unroll
    for (int mti = 0; mti < 2; mti++)
        #pragma unroll
        for (int h = 0; h < 2; h++) {
            int row = m0 + rg * 32 + mti * 16 + g + h * 8;
            kgp[mti][h] = g_keep + (size_t)(row / LSEQ) * NCOLP + wcol * 32 + 2 * tig;
        }

    float rs[4] = {0.f, 0.f, 0.f, 0.f};

    if (ntiles > 0) {
        // stage A once
        {
            const uint4* Ag = g_Afrag4 + (size_t)mt_ * 1024;
            cp16(smem_u32(sm) + t * 16, Ag + t);
            cp16(smem_u32(sm) + (t + 512) * 16, Ag + t + 512);
            CP_COMMIT();
            CP_WAIT0();
            __syncthreads();
        }
        const uint4* a0p = As4 + (rg * 2 + 0) * 128 + lane;
        const uint4* a1p = As4 + (rg * 2 + 1) * 128 + lane;

        for (int ti = 0; ti < ntiles; ti++) {
            const int ktile = rnk + ti * P;
            const uint4* bt = g_Bfrag4 + (size_t)ktile * 1024;
            const int koff = ktile * 128;

            #pragma unroll
            for (int cc2 = 0; cc2 < 2; cc2++) {
                const int cc = wcol * 2 + cc2;
                const uint4* bp = bt + cc * 128 + lane;
                uint4 b0 = __ldg(bp);
                uint4 b1 = __ldg(bp + 32);
                uint4 b2 = __ldg(bp + 64);
                uint4 b3 = __ldg(bp + 96);

                // init accumulators with keep terms from L2 (-inf -> ex2 -> 0)
                float c[2][2][4];
                #pragma unroll
                for (int mti = 0; mti < 2; mti++) {
                    #pragma unroll
                    for (int nt = 0; nt < 2; nt++) {
                        int co = koff + cc2 * 16 + nt * 8;
                        float2 k0 = *(const float2*)(kgp[mti][0] + co);
                        float2 k1 = *(const float2*)(kgp[mti][1] + co);
                        c[mti][nt][0] = k0.x; c[mti][nt][1] = k0.y;
                        c[mti][nt][2] = k1.x; c[mti][nt][3] = k1.y;
                    }
                }

                {
                    uint4 a0 = a0p[0],  a1 = a1p[0];
                    mma16(c[0][0], a0, b0.x, b0.y); mma16(c[0][1], a0, b0.z, b0.w);
                    mma16(c[1][0], a1, b0.x, b0.y); mma16(c[1][1], a1, b0.z, b0.w);
                }
                {
                    uint4 a0 = a0p[32], a1 = a1p[32];
                    mma16(c[0][0], a0, b1.x, b1.y); mma16(c[0][1], a0, b1.z, b1.w);
                    mma16(c[1][0], a1, b1.x, b1.y); mma16(c[1][1], a1, b1.z, b1.w);
                }
                {
                    uint4 a0 = a0p[64], a1 = a1p[64];
                    mma16(c[0][0], a0, b2.x, b2.y); mma16(c[0][1], a0, b2.z, b2.w);
                    mma16(c[1][0], a1, b2.x, b2.y); mma16(c[1][1], a1, b2.z, b2.w);
                }
                {
                    uint4 a0 = a0p[96], a1 = a1p[96];
                    mma16(c[0][0], a0, b3.x, b3.y); mma16(c[0][1], a0, b3.z, b3.w);
                    mma16(c[1][0], a1, b3.x, b3.y); mma16(c[1][1], a1, b3.z, b3.w);
                }

                #pragma unroll
                for (int mti = 0; mti < 2; mti++) {
                    #pragma unroll
                    for (int nt = 0; nt < 2; nt++) {
                        rs[mti * 2 + 0] += ex2f(c[mti][nt][0]) + ex2f(c[mti][nt][1]);
                        rs[mti * 2 + 1] += ex2f(c[mti][nt][2]) + ex2f(c[mti][nt][3]);
                    }
                }
            }
        }
    }

    // in-CTA: reduce 4 tig lanes, then 4 col-group slices
    #pragma unroll
    for (int q = 0; q < 4; q++) {
        rs[q] += __shfl_xor_sync(0xffffffffu, rs[q], 1);
        rs[q] += __shfl_xor_sync(0xffffffffu, rs[q], 2);
    }
    __syncthreads();   // A smem / sred reuse ordering
    if (tig == 0) {
        #pragma unroll
        for (int mti = 0; mti < 2; mti++)
            #pragma unroll
            for (int h = 0; h < 2; h++)
                sred[wcol * 128 + rg * 32 + mti * 16 + h * 8 + g] = rs[mti * 2 + h];
    }
    __syncthreads();
    if (t < 128) {
        float s = (sred[t] + sred[t + 128]) + (sred[t + 256] + sred[t + 384]);
        g_partS[rnk * NROW + m0 + t] = s;
    }

    // ============== Phase D: per-m-tile finalize + deterministic total ==============
    __shared__ unsigned int s_lastm;
    __threadfence();
    __syncthreads();
    if (t == 0)
        s_lastm = (atomicAdd(&g_mctr[mt_], 1u) == (unsigned)(P - 1)) ? 1u : 0u;
    __syncthreads();
    if (s_lastm) {
        __threadfence();
        double num = 0.0, den = 0.0;
        if (t < 128) {
            int r = m0 + t;
            float S = 0.f;
            for (int c = 0; c < P; c++) S += g_partS[c * NROW + r];
            float tv = g_tgt[r];
            S += __expf(tv);
            float nll = (S > 0.f) ? (logf(S) - tv) : logf((float)NCOL);
            if (log_mask[r] != 0) { num = (double)nll; den = 1.0; }
        }
        #pragma unroll
        for (int o = 16; o > 0; o >>= 1) {
            num += __shfl_down_sync(0xffffffffu, num, o);
            den += __shfl_down_sync(0xffffffffu, den, o);
        }
        __shared__ double swn[16];
        __shared__ double swd[16];
        if (lane == 0) { swn[w] = num; swd[w] = den; }
        __syncthreads();
        if (t == 0) {
            double n = 0.0, d = 0.0;
            #pragma unroll
            for (int i = 0; i < 4; i++) { n += swn[i]; d += swd[i]; }
            g_rn[mt_] = n;
            g_rd[mt_] = d;
            __threadfence();
            if (atomicAdd(&g_fin, 1u) == NMT - 1) {
                __threadfence();
                double tn = 0.0, td = 0.0;
                for (int i = 0; i < NMT; i++) { tn += g_rn[i]; td += g_rd[i]; }
                out[0] = (float)(tn / td);
                // self-reset for next graph replay
                for (int i = 0; i < NMT; i++) g_mctr[i] = 0u;
                g_fin = 0u;
                g_bar = 0u;
            }
        }
    }
}

// ---------------------------------------------------------------------------
extern "C" void kernel_launch(void* const* d_in, const int* in_sizes, int n_in,
                              void* d_out, int out_size) {
    const float* prec  = (const float*)d_in[0];  // [6400, 64]
    const float* embs  = (const float*)d_in[1];  // [6464, 64]
    const float* pop   = (const float*)d_in[2];  // [100001]
    const int*   items = (const int*)d_in[3];    // [6464]
    const int*   lmask = (const int*)d_in[4];    // [64, 100]
    float* out = (float*)d_out;

    cudaFuncSetAttribute(mega_kernel, cudaFuncAttributeMaxDynamicSharedMemorySize,
                         SMEM_BYTES);

    mega_kernel<<<TOTAL_CTAS, 512, SMEM_BYTES>>>(lmask, items, pop, prec, embs, out);
}